// round 7
// baseline (speedup 1.0000x reference)
#include <cuda_runtime.h>
#include <cuda_bf16.h>
#include <cstdint>

// Problem constants
#define B_   1024
#define N_   32
#define D_   512
#define H_   4
#define HD_  128
#define QKV_COLS 1536
#define M_ROWS   32768

// GEMM tiling (warp-level mma.sync path, int8 dual-pass)
#define BM 128
#define BN 128
#define CHUNKB 64                   // K-chunk bytes per row (k64 int8)
#define STAGES 4
#define ROWB 80                     // smem row stride bytes (64 data + 16 pad)
#define A_ST (BM * ROWB)            // 10240
#define ST_BYTES (2 * A_ST)         // 20480 (A tile + B tile)
#define GEMM_SMEM (STAGES * ST_BYTES)  // 81920

// Scratch (device globals — allocation-free per harness rules)
__device__ float  g_qkv[(size_t)M_ROWS * QKV_COLS];   // fp32 (B*N,1536)
__device__ float  g_ctx[(size_t)M_ROWS * D_];         // fp32 (B*N,512)
__device__ int8_t g_xh [(size_t)M_ROWS * 512];        // x hi digits
__device__ int8_t g_xm [(size_t)M_ROWS * 1024];       // x mid [a1|a0]
__device__ int8_t g_ch [(size_t)M_ROWS * 512];        // ctx hi
__device__ int8_t g_cm [(size_t)M_ROWS * 1024];       // ctx mid
__device__ int8_t g_w1h[(size_t)QKV_COLS * 512];      // W_in hi
__device__ int8_t g_w1m[(size_t)QKV_COLS * 1024];     // W_in mid [b0|b1]
__device__ int8_t g_w2h[(size_t)D_ * 512];            // W_out hi
__device__ int8_t g_w2m[(size_t)D_ * 1024];           // W_out mid
__device__ float  g_sx[M_ROWS], g_sc[M_ROWS], g_sw1[QKV_COLS], g_sw2[D_];

// ---------------------------------------------------------------------------
// PTX helpers (arch-agnostic: cp.async / ldmatrix / mma.sync)
// ---------------------------------------------------------------------------
__device__ __forceinline__ uint32_t smem_u32(const void* p) {
    uint32_t a;
    asm("{ .reg .u64 t; cvta.to.shared.u64 t, %1; cvt.u32.u64 %0, t; }"
        : "=r"(a) : "l"(p));
    return a;
}

__device__ __forceinline__ void cp_async16(uint32_t s, const void* g) {
    asm volatile("cp.async.cg.shared.global [%0], [%1], 16;"
                 :: "r"(s), "l"(g) : "memory");
}
#define CP_COMMIT() asm volatile("cp.async.commit_group;" ::: "memory")
#define CP_WAIT(n)  asm volatile("cp.async.wait_group %0;" :: "n"(n) : "memory")

__device__ __forceinline__ void ldsm4(uint32_t* r, uint32_t addr) {
    asm volatile("ldmatrix.sync.aligned.m8n8.x4.shared.b16 {%0,%1,%2,%3}, [%4];"
                 : "=r"(r[0]), "=r"(r[1]), "=r"(r[2]), "=r"(r[3]) : "r"(addr));
}

__device__ __forceinline__ void mma16832_s8(int* d, const uint32_t* a,
                                            const uint32_t* b) {
    asm volatile("mma.sync.aligned.m16n8k32.row.col.s32.s8.s8.s32 "
                 "{%0,%1,%2,%3}, {%4,%5,%6,%7}, {%8,%9}, {%0,%1,%2,%3};"
                 : "+r"(d[0]), "+r"(d[1]), "+r"(d[2]), "+r"(d[3])
                 : "r"(a[0]), "r"(a[1]), "r"(a[2]), "r"(a[3]),
                   "r"(b[0]), "r"(b[1]));
}

__device__ __forceinline__ uint32_t pack4b(int a, int b, int c, int d) {
    return (uint32_t)(a & 255) | ((uint32_t)(b & 255) << 8)
         | ((uint32_t)(c & 255) << 16) | ((uint32_t)(d & 255) << 24);
}

// ---------------------------------------------------------------------------
// Row quantization: fp32[rows,512] -> per-row scale + int8 digits.
//   val = s * (128*d1 + d0),  s = rowmax/16256,  |q| <= 16256, d0 in [-64,63]
//   hi buffer  : [d1]                 (512 B/row)
//   mid buffer : ASIDE ? [d1|d0] : [d0|d1]   (1024 B/row)
// ---------------------------------------------------------------------------
template<bool ASIDE>
__global__ __launch_bounds__(256)
void quant_rows(const float* __restrict__ src, int8_t* __restrict__ hi,
                int8_t* __restrict__ mid, float* __restrict__ scales, int nrows)
{
    int row = blockIdx.x * 8 + (threadIdx.x >> 5);
    if (row >= nrows) return;
    int lane = threadIdx.x & 31;

    float vals[16];
    const float4* s4 = (const float4*)(src + (size_t)row * 512 + lane * 16);
#pragma unroll
    for (int i = 0; i < 4; i++) {
        float4 v = s4[i];
        vals[i * 4 + 0] = v.x; vals[i * 4 + 1] = v.y;
        vals[i * 4 + 2] = v.z; vals[i * 4 + 3] = v.w;
    }
    float m = 0.f;
#pragma unroll
    for (int i = 0; i < 16; i++) m = fmaxf(m, fabsf(vals[i]));
#pragma unroll
    for (int o = 16; o; o >>= 1) m = fmaxf(m, __shfl_xor_sync(0xFFFFFFFFu, m, o));

    float inv = m > 0.f ? 16256.f / m : 0.f;
    int d1[16], d0[16];
#pragma unroll
    for (int i = 0; i < 16; i++) {
        int q = __float2int_rn(vals[i] * inv);
        int a1 = (q + 64) >> 7;          // round-to-nearest /128
        d1[i] = a1;
        d0[i] = q - (a1 << 7);           // in [-64, 63]
    }
    uint4 p1, p0;
    p1.x = pack4b(d1[0], d1[1], d1[2], d1[3]);
    p1.y = pack4b(d1[4], d1[5], d1[6], d1[7]);
    p1.z = pack4b(d1[8], d1[9], d1[10], d1[11]);
    p1.w = pack4b(d1[12], d1[13], d1[14], d1[15]);
    p0.x = pack4b(d0[0], d0[1], d0[2], d0[3]);
    p0.y = pack4b(d0[4], d0[5], d0[6], d0[7]);
    p0.z = pack4b(d0[8], d0[9], d0[10], d0[11]);
    p0.w = pack4b(d0[12], d0[13], d0[14], d0[15]);

    ((uint4*)(hi + (size_t)row * 512))[lane] = p1;
    uint4* mp = (uint4*)(mid + (size_t)row * 1024);
    if (ASIDE) { mp[lane] = p1; mp[lane + 32] = p0; }
    else       { mp[lane] = p0; mp[lane + 32] = p1; }

    if (lane == 0) scales[row] = m * (1.f / 16256.f);
}

// ---------------------------------------------------------------------------
// IMMA GEMM: C[M,Nout] (+)= wscale*sA_i*sB_j * (A_int8[M,KB] @ B_int8[Nout,KB]^T)
// Same proven skeleton as the bf16 kernel: CTA 128x128, 8 warps (2x4),
// warp tile 64x32, 64B K-chunk, 4-stage cp.async, one barrier per chunk.
// NKT = number of 64B chunks, ACC = accumulate into C (and add bias).
// ---------------------------------------------------------------------------
template<int NKT, int KB, bool ACC>
__global__ __launch_bounds__(256, 2)
void gemm_i8(const int8_t* __restrict__ A, const int8_t* __restrict__ Bm,
             const float* __restrict__ sAv, const float* __restrict__ sBv,
             const float* __restrict__ bias, float* __restrict__ C,
             int Nout, float wscale)
{
    extern __shared__ __align__(128) char smem[];
    const int tid  = threadIdx.x;
    const int wid  = tid >> 5;
    const int lane = tid & 31;
    const int m0 = blockIdx.y * BM;
    const int n0 = blockIdx.x * BN;
    const int warp_m = (wid >> 2) * 64;   // 0 or 64
    const int warp_n = (wid & 3) * 32;    // 0..96
    const uint32_t sbase = smem_u32(smem);

    const int lr = tid >> 2;        // 0..63 base row
    const int lc = tid & 3;         // 16B chunk in row

    int acc[4][4][4];
#pragma unroll
    for (int mi = 0; mi < 4; mi++)
#pragma unroll
        for (int ni = 0; ni < 4; ni++)
#pragma unroll
            for (int r = 0; r < 4; r++) acc[mi][ni][r] = 0;

    auto load_stage = [&](int kc, int buf) {
        const uint32_t as = sbase + buf * ST_BYTES;
        const uint32_t bs = as + A_ST;
        const int8_t* Ag = A  + (size_t)m0 * KB + kc * CHUNKB;
        const int8_t* Bg = Bm + (size_t)n0 * KB + kc * CHUNKB;
#pragma unroll
        for (int i = 0; i < 2; i++) {
            int r = lr + i * 64;
            cp_async16(as + r * ROWB + lc * 16, Ag + (size_t)r * KB + lc * 16);
        }
#pragma unroll
        for (int i = 0; i < 2; i++) {
            int r = lr + i * 64;
            cp_async16(bs + r * ROWB + lc * 16, Bg + (size_t)r * KB + lc * 16);
        }
        CP_COMMIT();
    };

    load_stage(0, 0);
    load_stage(1, 1);
    load_stage(2, 2);

    const uint32_t a_addr0 = sbase + (warp_m + (lane & 15)) * ROWB + (lane >> 4) * 16;
    const uint32_t b_addr0 = sbase + A_ST
                           + (warp_n + ((lane >> 4) << 3) + (lane & 7)) * ROWB
                           + (((lane >> 3) & 1) << 4);

    for (int k = 0; k < NKT; k++) {
        const int buf = k & 3;
        if (k < NKT - 2)       { CP_WAIT(2); }
        else if (k == NKT - 2) { CP_WAIT(1); }
        else                   { CP_WAIT(0); }
        __syncthreads();

        const uint32_t soff = buf * ST_BYTES;
#pragma unroll
        for (int ks = 0; ks < 2; ks++) {            // two k32 steps per chunk
            uint32_t af[4][4], bf[2][4];
#pragma unroll
            for (int mi = 0; mi < 4; mi++)
                ldsm4(af[mi], a_addr0 + soff + mi * 16 * ROWB + ks * 32);
            ldsm4(bf[0], b_addr0 + soff + ks * 32);
            ldsm4(bf[1], b_addr0 + soff + 16 * ROWB + ks * 32);
#pragma unroll
            for (int mi = 0; mi < 4; mi++) {
#pragma unroll
                for (int ni = 0; ni < 4; ni++) {
                    const uint32_t* bp = (ni < 2) ? &bf[0][(ni & 1) * 2]
                                                  : &bf[1][(ni & 1) * 2];
                    mma16832_s8(acc[mi][ni], af[mi], bp);
                }
            }
        }
        // no trailing barrier: iter-k writes target buf (k-1)&3, whose
        // readers all passed this iteration's top barrier (ring distance).
        const int kn = k + 3;
        if (kn < NKT) load_stage(kn, kn & 3);
    }

    // epilogue: scaled int32 -> fp32 (+ old C + bias when ACC)
#pragma unroll
    for (int mi = 0; mi < 4; mi++) {
#pragma unroll
        for (int ni = 0; ni < 4; ni++) {
            int row = m0 + warp_m + mi * 16 + (lane >> 2);
            int col = n0 + warp_n + ni * 8 + (lane & 3) * 2;
            float fa0 = sAv[row] * wscale;
            float fa1 = sAv[row + 8] * wscale;
            float fb0 = sBv[col], fb1 = sBv[col + 1];
            float2 v0, v1;
            v0.x = fa0 * fb0 * (float)acc[mi][ni][0];
            v0.y = fa0 * fb1 * (float)acc[mi][ni][1];
            v1.x = fa1 * fb0 * (float)acc[mi][ni][2];
            v1.y = fa1 * fb1 * (float)acc[mi][ni][3];
            float* p0 = C + (size_t)row * Nout + col;
            float* p1 = C + (size_t)(row + 8) * Nout + col;
            if (ACC) {
                float b0 = bias[col], b1 = bias[col + 1];
                float2 o0 = *(float2*)p0, o1 = *(float2*)p1;
                v0.x += o0.x + b0; v0.y += o0.y + b1;
                v1.x += o1.x + b0; v1.y += o1.y + b1;
            }
            *(float2*)p0 = v0;
            *(float2*)p1 = v1;
        }
    }
}

// ---------------------------------------------------------------------------
// Attention: one block per (b, h). 32 q x 32 k x 128 d. fp32 in/out.
// ---------------------------------------------------------------------------
__global__ __launch_bounds__(128)
void attn_kernel(const float* __restrict__ qkv,
                 const unsigned char* __restrict__ pad,
                 float* __restrict__ ctx)
{
    __shared__ float qs[32 * 129];
    __shared__ float ks[32 * 129];
    __shared__ float vs[32 * 129];
    __shared__ float sc[32 * 33];
    __shared__ int   spad[32];

    const int b = blockIdx.x >> 2;
    const int h = blockIdx.x & 3;
    const int tid = threadIdx.x;

    const float* base = qkv + (size_t)b * N_ * QKV_COLS + h * HD_;

    for (int idx = tid; idx < N_ * HD_; idx += 128) {
        int r = idx >> 7, c = idx & 127;
        qs[r * 129 + c] = base[(size_t)r * QKV_COLS            + c];
        ks[r * 129 + c] = base[(size_t)r * QKV_COLS + D_     + c];
        vs[r * 129 + c] = base[(size_t)r * QKV_COLS + 2 * D_ + c];
    }
    if (tid < 32) spad[tid] = pad[b * N_ + tid];
    __syncthreads();

    const int q = tid >> 2;
    const int kbase = (tid & 3) * 8;
    const float* qrow = &qs[q * 129];

    float acc[8];
#pragma unroll
    for (int i = 0; i < 8; i++) acc[i] = 0.f;

    for (int c0 = 0; c0 < HD_; c0 += 16) {
        float qreg[16];
#pragma unroll
        for (int c = 0; c < 16; c++) qreg[c] = qrow[c0 + c];
#pragma unroll
        for (int i = 0; i < 8; i++) {
            const float* krow = &ks[(kbase + i) * 129 + c0];
#pragma unroll
            for (int c = 0; c < 16; c++) acc[i] += qreg[c] * krow[c];
        }
    }

    const float scale = 0.08838834764831845f;  // 1/sqrt(128)
#pragma unroll
    for (int i = 0; i < 8; i++) {
        int k = kbase + i;
        float s = (k == q || spad[k]) ? -1e30f : acc[i] * scale;
        sc[q * 33 + k] = s;
    }
    __syncthreads();

    if (tid < 32) {
        float m = -1e30f;
#pragma unroll
        for (int k = 0; k < 32; k++) m = fmaxf(m, sc[tid * 33 + k]);
        float sum = 0.f;
#pragma unroll
        for (int k = 0; k < 32; k++) {
            float e = __expf(sc[tid * 33 + k] - m);
            sc[tid * 33 + k] = e;
            sum += e;
        }
        float inv = 1.f / sum;
#pragma unroll
        for (int k = 0; k < 32; k++) sc[tid * 33 + k] *= inv;
    }
    __syncthreads();

    {
        const int dq = tid & 3;
        float o[32];
#pragma unroll
        for (int j = 0; j < 32; j++) o[j] = 0.f;
        for (int k = 0; k < 32; k++) {
            float p = sc[q * 33 + k];
            const float* vrow = &vs[k * 129 + dq];
#pragma unroll
            for (int j = 0; j < 32; j++) o[j] += p * vrow[4 * j];
        }
        float* stg = &ks[q * 129 + dq];
#pragma unroll
        for (int j = 0; j < 32; j++) stg[4 * j] = o[j];
    }
    __syncthreads();

    float* outp = ctx + (size_t)b * N_ * D_ + h * HD_;
    for (int idx = tid; idx < N_ * HD_; idx += 128) {
        int r = idx >> 7, c = idx & 127;
        outp[(size_t)r * D_ + c] = ks[r * 129 + c];
    }
}

// ---------------------------------------------------------------------------
// Launch
// ---------------------------------------------------------------------------
extern "C" void kernel_launch(void* const* d_in, const int* in_sizes, int n_in,
                              void* d_out, int out_size)
{
    const float*         x     = (const float*)d_in[0];
    const unsigned char* pmask = (const unsigned char*)d_in[1];
    const float*         w_in  = (const float*)d_in[2];
    const float*         b_in  = (const float*)d_in[3];
    const float*         w_out = (const float*)d_in[4];
    const float*         b_out = (const float*)d_in[5];
    float*               out   = (float*)d_out;

    void *p;
    cudaGetSymbolAddress(&p, g_qkv);  float*  qkv = (float*)p;
    cudaGetSymbolAddress(&p, g_ctx);  float*  ctx = (float*)p;
    cudaGetSymbolAddress(&p, g_xh);   int8_t* xh  = (int8_t*)p;
    cudaGetSymbolAddress(&p, g_xm);   int8_t* xm  = (int8_t*)p;
    cudaGetSymbolAddress(&p, g_ch);   int8_t* ch  = (int8_t*)p;
    cudaGetSymbolAddress(&p, g_cm);   int8_t* cm  = (int8_t*)p;
    cudaGetSymbolAddress(&p, g_w1h);  int8_t* w1h = (int8_t*)p;
    cudaGetSymbolAddress(&p, g_w1m);  int8_t* w1m = (int8_t*)p;
    cudaGetSymbolAddress(&p, g_w2h);  int8_t* w2h = (int8_t*)p;
    cudaGetSymbolAddress(&p, g_w2m);  int8_t* w2m = (int8_t*)p;
    cudaGetSymbolAddress(&p, g_sx);   float*  sx  = (float*)p;
    cudaGetSymbolAddress(&p, g_sc);   float*  scx = (float*)p;
    cudaGetSymbolAddress(&p, g_sw1);  float*  sw1 = (float*)p;
    cudaGetSymbolAddress(&p, g_sw2);  float*  sw2 = (float*)p;

    cudaFuncSetAttribute((const void*)gemm_i8<8, 512, false>,
                         cudaFuncAttributeMaxDynamicSharedMemorySize, GEMM_SMEM);
    cudaFuncSetAttribute((const void*)gemm_i8<16, 1024, true>,
                         cudaFuncAttributeMaxDynamicSharedMemorySize, GEMM_SMEM);

    // quantize inputs + weights
    quant_rows<true ><<<M_ROWS / 8, 256>>>(x, xh, xm, sx, M_ROWS);
    quant_rows<false><<<QKV_COLS / 8, 256>>>(w_in, w1h, w1m, sw1, QKV_COLS);
    quant_rows<false><<<D_ / 8, 256>>>(w_out, w2h, w2m, sw2, D_);

    // 1) QKV projection: hi pass (a1@b1, weight 16384) + mid pass (+bias)
    {
        dim3 grid(QKV_COLS / BN, M_ROWS / BM);   // (12, 256)
        gemm_i8<8, 512, false><<<grid, 256, GEMM_SMEM>>>(
            xh, w1h, sx, sw1, nullptr, qkv, QKV_COLS, 16384.f);
        gemm_i8<16, 1024, true><<<grid, 256, GEMM_SMEM>>>(
            xm, w1m, sx, sw1, b_in, qkv, QKV_COLS, 128.f);
    }

    // 2) attention (fp32), then quantize ctx
    attn_kernel<<<B_ * H_, 128>>>(qkv, pmask, ctx);
    quant_rows<true><<<M_ROWS / 8, 256>>>(ctx, ch, cm, scx, M_ROWS);

    // 3) output projection
    {
        dim3 grid(D_ / BN, M_ROWS / BM);         // (4, 256)
        gemm_i8<8, 512, false><<<grid, 256, GEMM_SMEM>>>(
            ch, w2h, scx, sw2, nullptr, out, D_, 16384.f);
        gemm_i8<16, 1024, true><<<grid, 256, GEMM_SMEM>>>(
            cm, w2m, scx, sw2, b_out, out, D_, 128.f);
    }
}

// round 8
// speedup vs baseline: 1.7457x; 1.7457x over previous
#include <cuda_runtime.h>
#include <cuda_fp16.h>
#include <cstdint>

// Problem constants
#define B_   1024
#define N_   32
#define D_   512
#define H_   4
#define HD_  128
#define QKV_COLS 1536
#define M_ROWS   32768
#define KT   1024              // doubled K (2 * 512): [hi | correction]

// GEMM tiling (warp-level mma.sync path — compiles for compute_103)
#define BM 128
#define BN 128
#define BK 32                       // fp16 per K-chunk (64B data per row)
#define STAGES 4
#define ROWB 80                     // smem row stride bytes (64 data + 16 pad)
#define A_ST (BM * ROWB)            // 10240
#define ST_BYTES (2 * A_ST)         // 20480 (A tile + B tile)
#define GEMM_SMEM (STAGES * ST_BYTES)  // 81920
#define NK (KT / BK)                // 32

// Scratch (device globals — allocation-free per harness rules)
__device__ float  g_qkv [(size_t)M_ROWS * QKV_COLS];  // fp32 (B*N,1536)
__device__ __half g_xa  [(size_t)M_ROWS * KT];        // x   [ah | ah/128]
__device__ __half g_ctxa[(size_t)M_ROWS * KT];        // ctx [ch | ch/128]
__device__ __half g_wina[(size_t)QKV_COLS * KT];      // W_in  [bh | 128*bl]
__device__ __half g_wouta[(size_t)D_ * KT];           // W_out [bh | 128*bl]

// ---------------------------------------------------------------------------
// PTX helpers (all arch-agnostic: cp.async / ldmatrix / mma.sync)
// ---------------------------------------------------------------------------
__device__ __forceinline__ uint32_t smem_u32(const void* p) {
    uint32_t a;
    asm("{ .reg .u64 t; cvta.to.shared.u64 t, %1; cvt.u32.u64 %0, t; }"
        : "=r"(a) : "l"(p));
    return a;
}

__device__ __forceinline__ void cp_async16(uint32_t s, const void* g) {
    asm volatile("cp.async.cg.shared.global [%0], [%1], 16;"
                 :: "r"(s), "l"(g) : "memory");
}
#define CP_COMMIT() asm volatile("cp.async.commit_group;" ::: "memory")
#define CP_WAIT(n)  asm volatile("cp.async.wait_group %0;" :: "n"(n) : "memory")

__device__ __forceinline__ void ldsm4(uint32_t* r, uint32_t addr) {
    asm volatile("ldmatrix.sync.aligned.m8n8.x4.shared.b16 {%0,%1,%2,%3}, [%4];"
                 : "=r"(r[0]), "=r"(r[1]), "=r"(r[2]), "=r"(r[3]) : "r"(addr));
}

__device__ __forceinline__ void mma16816(float* d, const uint32_t* a,
                                         const uint32_t* b) {
    asm volatile("mma.sync.aligned.m16n8k16.row.col.f32.f16.f16.f32 "
                 "{%0,%1,%2,%3}, {%4,%5,%6,%7}, {%8,%9}, {%0,%1,%2,%3};"
                 : "+f"(d[0]), "+f"(d[1]), "+f"(d[2]), "+f"(d[3])
                 : "r"(a[0]), "r"(a[1]), "r"(a[2]), "r"(a[3]),
                   "r"(b[0]), "r"(b[1]));
}

// ---------------------------------------------------------------------------
// Conversion kernels (fp32 K=512 -> dual fp16 K=1024)
// ---------------------------------------------------------------------------
// A-side: [ah | ah/128]
__global__ void conv_a(const float* __restrict__ src, __half* __restrict__ dst,
                       int total4) {
    int idx = blockIdx.x * 256 + threadIdx.x;
    if (idx >= total4) return;
    int row = idx >> 7;            // 128 float4 per 512-col row
    int c4  = (idx & 127) << 2;
    float4 v = *(const float4*)(src + (size_t)row * 512 + c4);
    __half2 h01 = __floats2half2_rn(v.x, v.y);
    __half2 h23 = __floats2half2_rn(v.z, v.w);
    const float s = 0.0078125f;    // 1/128
    __half2 l01 = __floats2half2_rn(v.x * s, v.y * s);
    __half2 l23 = __floats2half2_rn(v.z * s, v.w * s);
    __half* d = dst + (size_t)row * KT + c4;
    ((__half2*)(d      ))[0] = h01;
    ((__half2*)(d      ))[1] = h23;
    ((__half2*)(d + 512))[0] = l01;
    ((__half2*)(d + 512))[1] = l23;
}

// B-side: [bh | 128*(B - bh)]
__global__ void conv_b(const float* __restrict__ src, __half* __restrict__ dst,
                       int total4) {
    int idx = blockIdx.x * 256 + threadIdx.x;
    if (idx >= total4) return;
    int row = idx >> 7;
    int c4  = (idx & 127) << 2;
    float4 v = *(const float4*)(src + (size_t)row * 512 + c4);
    __half h0 = __float2half_rn(v.x), h1 = __float2half_rn(v.y);
    __half h2 = __float2half_rn(v.z), h3 = __float2half_rn(v.w);
    float l0 = (v.x - __half2float(h0)) * 128.f;
    float l1 = (v.y - __half2float(h1)) * 128.f;
    float l2 = (v.z - __half2float(h2)) * 128.f;
    float l3 = (v.w - __half2float(h3)) * 128.f;
    __half* d = dst + (size_t)row * KT + c4;
    ((__half2*)(d      ))[0] = __halves2half2(h0, h1);
    ((__half2*)(d      ))[1] = __halves2half2(h2, h3);
    ((__half2*)(d + 512))[0] = __floats2half2_rn(l0, l1);
    ((__half2*)(d + 512))[1] = __floats2half2_rn(l2, l3);
}

// ---------------------------------------------------------------------------
// HMMA GEMM: C[M, Nout](fp32) = A[M, KT](fp16) @ B[Nout, KT](fp16)^T + bias
// CTA 128x128, 8 warps (2x4), warp tile 64x32, K-chunk 32, 4-stage cp.async.
// smem rows stride 80B -> every 8-row ldmatrix phase covers all 32 banks.
// One barrier per K-chunk (ring distance makes the trailing barrier redundant).
// ---------------------------------------------------------------------------
__global__ __launch_bounds__(256, 2)
void gemm_mma(const __half* __restrict__ A,
              const __half* __restrict__ Bm,
              const float* __restrict__ bias, float* __restrict__ C, int Nout)
{
    extern __shared__ __align__(128) char smem[];
    const int tid  = threadIdx.x;
    const int wid  = tid >> 5;
    const int lane = tid & 31;
    const int m0 = blockIdx.y * BM;
    const int n0 = blockIdx.x * BN;
    const int warp_m = (wid >> 2) * 64;   // 0 or 64
    const int warp_n = (wid & 3) * 32;    // 0..96
    const uint32_t sbase = smem_u32(smem);

    // load thread mapping: 512 16B-chunks per tile, 2 per thread per tile
    const int lr = tid >> 2;        // 0..63 base row
    const int lc = tid & 3;         // 16B chunk in row

    float acc[4][4][4];
#pragma unroll
    for (int mi = 0; mi < 4; mi++)
#pragma unroll
        for (int ni = 0; ni < 4; ni++)
#pragma unroll
            for (int r = 0; r < 4; r++) acc[mi][ni][r] = 0.f;

    auto load_stage = [&](int kc, int buf) {
        const uint32_t as = sbase + buf * ST_BYTES;
        const uint32_t bs = as + A_ST;
        const __half* Ag = A  + (size_t)m0 * KT + kc * BK;
        const __half* Bg = Bm + (size_t)n0 * KT + kc * BK;
#pragma unroll
        for (int i = 0; i < 2; i++) {
            int r = lr + i * 64;
            cp_async16(as + r * ROWB + lc * 16, Ag + (size_t)r * KT + lc * 8);
        }
#pragma unroll
        for (int i = 0; i < 2; i++) {
            int r = lr + i * 64;
            cp_async16(bs + r * ROWB + lc * 16, Bg + (size_t)r * KT + lc * 8);
        }
        CP_COMMIT();
    };

    load_stage(0, 0);
    load_stage(1, 1);
    load_stage(2, 2);

    // fragment addresses (constant per thread, add stage/k offsets)
    const uint32_t a_addr0 = sbase + (warp_m + (lane & 15)) * ROWB + (lane >> 4) * 16;
    const uint32_t b_addr0 = sbase + A_ST
                           + (warp_n + ((lane >> 4) << 3) + (lane & 7)) * ROWB
                           + (((lane >> 3) & 1) << 4);

    for (int k = 0; k < NK; k++) {
        const int buf = k & 3;
        if (k < NK - 2)       { CP_WAIT(2); }
        else if (k == NK - 2) { CP_WAIT(1); }
        else                  { CP_WAIT(0); }
        __syncthreads();

        const uint32_t soff = buf * ST_BYTES;
#pragma unroll
        for (int ks = 0; ks < 2; ks++) {            // two k16 steps per chunk
            uint32_t af[4][4], bf[2][4];
#pragma unroll
            for (int mi = 0; mi < 4; mi++)
                ldsm4(af[mi], a_addr0 + soff + mi * 16 * ROWB + ks * 32);
            ldsm4(bf[0], b_addr0 + soff + ks * 32);
            ldsm4(bf[1], b_addr0 + soff + 16 * ROWB + ks * 32);
#pragma unroll
            for (int mi = 0; mi < 4; mi++) {
#pragma unroll
                for (int ni = 0; ni < 4; ni++) {
                    const uint32_t* bp = (ni < 2) ? &bf[0][(ni & 1) * 2]
                                                  : &bf[1][(ni & 1) * 2];
                    mma16816(acc[mi][ni], af[mi], bp);
                }
            }
        }
        // no trailing barrier: iter-k writes target buf (k+3)&3 = (k-1)&3,
        // whose readers (iter k-1 ldsm) all passed this iter's top barrier.
        const int kn = k + 3;
        if (kn < NK) load_stage(kn, kn & 3);
    }

    // epilogue: bias + fp32 store (float2 per reg-pair)
#pragma unroll
    for (int mi = 0; mi < 4; mi++) {
#pragma unroll
        for (int ni = 0; ni < 4; ni++) {
            int row = m0 + warp_m + mi * 16 + (lane >> 2);
            int col = n0 + warp_n + ni * 8 + (lane & 3) * 2;
            float b0 = bias[col], b1 = bias[col + 1];
            float2 v0 = make_float2(acc[mi][ni][0] + b0, acc[mi][ni][1] + b1);
            float2 v1 = make_float2(acc[mi][ni][2] + b0, acc[mi][ni][3] + b1);
            *(float2*)(C + (size_t)row * Nout + col)       = v0;
            *(float2*)(C + (size_t)(row + 8) * Nout + col) = v1;
        }
    }
}

// ---------------------------------------------------------------------------
// Attention: one block per (b, h). 32 q x 32 k x 128 d. Output written
// directly in dual-fp16 A-side layout [ch | ch/128] into g_ctxa.
// ---------------------------------------------------------------------------
__global__ __launch_bounds__(128)
void attn_kernel(const float* __restrict__ qkv,
                 const unsigned char* __restrict__ pad,
                 __half* __restrict__ ctxa)
{
    __shared__ float qs[32 * 129];
    __shared__ float ks[32 * 129];
    __shared__ float vs[32 * 129];
    __shared__ float sc[32 * 33];
    __shared__ int   spad[32];

    const int b = blockIdx.x >> 2;
    const int h = blockIdx.x & 3;
    const int tid = threadIdx.x;

    const float* base = qkv + (size_t)b * N_ * QKV_COLS + h * HD_;

    for (int idx = tid; idx < N_ * HD_; idx += 128) {
        int r = idx >> 7, c = idx & 127;
        qs[r * 129 + c] = base[(size_t)r * QKV_COLS            + c];
        ks[r * 129 + c] = base[(size_t)r * QKV_COLS + D_     + c];
        vs[r * 129 + c] = base[(size_t)r * QKV_COLS + 2 * D_ + c];
    }
    if (tid < 32) spad[tid] = pad[b * N_ + tid];
    __syncthreads();

    const int q = tid >> 2;
    const int kbase = (tid & 3) * 8;
    const float* qrow = &qs[q * 129];

    float acc[8];
#pragma unroll
    for (int i = 0; i < 8; i++) acc[i] = 0.f;

    for (int c0 = 0; c0 < HD_; c0 += 16) {
        float qreg[16];
#pragma unroll
        for (int c = 0; c < 16; c++) qreg[c] = qrow[c0 + c];
#pragma unroll
        for (int i = 0; i < 8; i++) {
            const float* krow = &ks[(kbase + i) * 129 + c0];
#pragma unroll
            for (int c = 0; c < 16; c++) acc[i] += qreg[c] * krow[c];
        }
    }

    const float scale = 0.08838834764831845f;  // 1/sqrt(128)
#pragma unroll
    for (int i = 0; i < 8; i++) {
        int k = kbase + i;
        float s = (k == q || spad[k]) ? -1e30f : acc[i] * scale;
        sc[q * 33 + k] = s;
    }
    __syncthreads();

    if (tid < 32) {
        float m = -1e30f;
#pragma unroll
        for (int k = 0; k < 32; k++) m = fmaxf(m, sc[tid * 33 + k]);
        float sum = 0.f;
#pragma unroll
        for (int k = 0; k < 32; k++) {
            float e = __expf(sc[tid * 33 + k] - m);
            sc[tid * 33 + k] = e;
            sum += e;
        }
        float inv = 1.f / sum;
#pragma unroll
        for (int k = 0; k < 32; k++) sc[tid * 33 + k] *= inv;
    }
    __syncthreads();

    {
        const int dq = tid & 3;
        float o[32];
#pragma unroll
        for (int j = 0; j < 32; j++) o[j] = 0.f;
        for (int k = 0; k < 32; k++) {
            float p = sc[q * 33 + k];
            const float* vrow = &vs[k * 129 + dq];
#pragma unroll
            for (int j = 0; j < 32; j++) o[j] += p * vrow[4 * j];
        }
        float* stg = &ks[q * 129 + dq];
#pragma unroll
        for (int j = 0; j < 32; j++) stg[4 * j] = o[j];
    }
    __syncthreads();

    // write dual-fp16 ctx: [ch | ch/128]
    __half* outa = ctxa + (size_t)b * N_ * KT + h * HD_;
    for (int idx = tid; idx < N_ * HD_; idx += 128) {
        int r = idx >> 7, c = idx & 127;
        float v = ks[r * 129 + c];
        __half hi = __float2half_rn(v);
        __half* p = outa + (size_t)r * KT + c;
        p[0]   = hi;
        p[512] = __float2half_rn(v * 0.0078125f);
    }
}

// ---------------------------------------------------------------------------
// Launch
// ---------------------------------------------------------------------------
extern "C" void kernel_launch(void* const* d_in, const int* in_sizes, int n_in,
                              void* d_out, int out_size)
{
    const float*         x     = (const float*)d_in[0];
    const unsigned char* pmask = (const unsigned char*)d_in[1];
    const float*         w_in  = (const float*)d_in[2];
    const float*         b_in  = (const float*)d_in[3];
    const float*         w_out = (const float*)d_in[4];
    const float*         b_out = (const float*)d_in[5];
    float*               out   = (float*)d_out;

    void *qkv_p, *xa_p, *ctxa_p, *wina_p, *wouta_p;
    cudaGetSymbolAddress(&qkv_p,   g_qkv);
    cudaGetSymbolAddress(&xa_p,    g_xa);
    cudaGetSymbolAddress(&ctxa_p,  g_ctxa);
    cudaGetSymbolAddress(&wina_p,  g_wina);
    cudaGetSymbolAddress(&wouta_p, g_wouta);
    float*  qkv   = (float*)qkv_p;
    __half* xa    = (__half*)xa_p;
    __half* ctxa  = (__half*)ctxa_p;
    __half* wina  = (__half*)wina_p;
    __half* wouta = (__half*)wouta_p;

    cudaFuncSetAttribute(gemm_mma, cudaFuncAttributeMaxDynamicSharedMemorySize,
                         GEMM_SMEM);

    // dual-fp16 conversions
    {
        int t4 = M_ROWS * 128;
        conv_a<<<(t4 + 255) / 256, 256>>>(x, xa, t4);
    }
    {
        int t4 = QKV_COLS * 128;
        conv_b<<<(t4 + 255) / 256, 256>>>(w_in, wina, t4);
    }
    {
        int t4 = D_ * 128;
        conv_b<<<(t4 + 255) / 256, 256>>>(w_out, wouta, t4);
    }

    // 1) QKV projection: (32768 x 1536)
    {
        dim3 grid(QKV_COLS / BN, M_ROWS / BM);   // (12, 256)
        gemm_mma<<<grid, 256, GEMM_SMEM>>>(xa, wina, b_in, qkv, QKV_COLS);
    }

    // 2) attention (writes dual-fp16 ctx)
    attn_kernel<<<B_ * H_, 128>>>(qkv, pmask, ctxa);

    // 3) output projection: (32768 x 512)
    {
        dim3 grid(D_ / BN, M_ROWS / BM);         // (4, 256)
        gemm_mma<<<grid, 256, GEMM_SMEM>>>(ctxa, wouta, b_out, out, D_);
    }
}

// round 9
// speedup vs baseline: 2.2985x; 1.3167x over previous
#include <cuda_runtime.h>
#include <cuda_bf16.h>
#include <cstdint>

// Problem constants
#define B_   1024
#define N_   32
#define D_   512
#define H_   4
#define HD_  128
#define QKV_COLS 1536
#define M_ROWS   32768
#define KT   1536              // tripled K (3 * 512)

// GEMM tiling (warp-level mma.sync path — compiles for compute_103)
#define BM 128
#define BN 128
#define BK 32                       // bf16 per K-chunk (64B data per row)
#define STAGES 4
#define ROWB 80                     // smem row stride bytes (64 data + 16 pad)
#define A_ST (BM * ROWB)            // 10240
#define ST_BYTES (2 * A_ST)         // 20480 (A tile + B tile)
#define GEMM_SMEM (STAGES * ST_BYTES)  // 81920
#define NK (KT / BK)                // 48

// Scratch (device globals — allocation-free per harness rules)
__device__ float         g_qkv [(size_t)M_ROWS * QKV_COLS];  // fp32 (B*N,1536)
__device__ __nv_bfloat16 g_xa  [(size_t)M_ROWS * KT];        // x  split [Ah|Al|Ah]
__device__ __nv_bfloat16 g_ctxa[(size_t)M_ROWS * KT];        // ctx split [Ah|Al|Ah]
__device__ __nv_bfloat16 g_wina[(size_t)QKV_COLS * KT];      // W_in  split [Bh|Bh|Bl]
__device__ __nv_bfloat16 g_wouta[(size_t)D_ * KT];           // W_out split [Bh|Bh|Bl]

// ---------------------------------------------------------------------------
// PTX helpers (all arch-agnostic: cp.async / ldmatrix / mma.sync)
// ---------------------------------------------------------------------------
__device__ __forceinline__ uint32_t smem_u32(const void* p) {
    uint32_t a;
    asm("{ .reg .u64 t; cvta.to.shared.u64 t, %1; cvt.u32.u64 %0, t; }"
        : "=r"(a) : "l"(p));
    return a;
}

__device__ __forceinline__ void cp_async16(uint32_t s, const void* g) {
    asm volatile("cp.async.cg.shared.global [%0], [%1], 16;"
                 :: "r"(s), "l"(g) : "memory");
}
#define CP_COMMIT() asm volatile("cp.async.commit_group;" ::: "memory")
#define CP_WAIT(n)  asm volatile("cp.async.wait_group %0;" :: "n"(n) : "memory")

__device__ __forceinline__ void ldsm4(uint32_t* r, uint32_t addr) {
    asm volatile("ldmatrix.sync.aligned.m8n8.x4.shared.b16 {%0,%1,%2,%3}, [%4];"
                 : "=r"(r[0]), "=r"(r[1]), "=r"(r[2]), "=r"(r[3]) : "r"(addr));
}

__device__ __forceinline__ void mma16816(float* d, const uint32_t* a,
                                         const uint32_t* b) {
    asm volatile("mma.sync.aligned.m16n8k16.row.col.f32.bf16.bf16.f32 "
                 "{%0,%1,%2,%3}, {%4,%5,%6,%7}, {%8,%9}, {%0,%1,%2,%3};"
                 : "+f"(d[0]), "+f"(d[1]), "+f"(d[2]), "+f"(d[3])
                 : "r"(a[0]), "r"(a[1]), "r"(a[2]), "r"(a[3]),
                   "r"(b[0]), "r"(b[1]));
}

// ---------------------------------------------------------------------------
// Split-precision conversion kernels (fp32 -> tripled bf16, K=512 -> 1536)
// ---------------------------------------------------------------------------
__device__ __forceinline__ void split_bf16(float v, __nv_bfloat16& hi, __nv_bfloat16& lo) {
    hi = __float2bfloat16_rn(v);
    lo = __float2bfloat16_rn(v - __bfloat162float(hi));
}

// A-side layout: [Ah | Al | Ah]
__global__ void conv_a(const float* __restrict__ src, __nv_bfloat16* __restrict__ dst,
                       int total4) {
    int idx = blockIdx.x * 256 + threadIdx.x;
    if (idx >= total4) return;
    int row = idx >> 7;            // 128 float4 per 512-col row
    int c4  = (idx & 127) << 2;
    float4 v = *(const float4*)(src + (size_t)row * 512 + c4);
    __nv_bfloat16 h0, h1, h2, h3, l0, l1, l2, l3;
    split_bf16(v.x, h0, l0); split_bf16(v.y, h1, l1);
    split_bf16(v.z, h2, l2); split_bf16(v.w, h3, l3);
    __nv_bfloat16* d = dst + (size_t)row * KT + c4;
    ((__nv_bfloat162*)(d       ))[0] = __nv_bfloat162(h0, h1);
    ((__nv_bfloat162*)(d       ))[1] = __nv_bfloat162(h2, h3);
    ((__nv_bfloat162*)(d +  512))[0] = __nv_bfloat162(l0, l1);
    ((__nv_bfloat162*)(d +  512))[1] = __nv_bfloat162(l2, l3);
    ((__nv_bfloat162*)(d + 1024))[0] = __nv_bfloat162(h0, h1);
    ((__nv_bfloat162*)(d + 1024))[1] = __nv_bfloat162(h2, h3);
}

// B-side layout: [Bh | Bh | Bl]
__global__ void conv_b(const float* __restrict__ src, __nv_bfloat16* __restrict__ dst,
                       int total4) {
    int idx = blockIdx.x * 256 + threadIdx.x;
    if (idx >= total4) return;
    int row = idx >> 7;
    int c4  = (idx & 127) << 2;
    float4 v = *(const float4*)(src + (size_t)row * 512 + c4);
    __nv_bfloat16 h0, h1, h2, h3, l0, l1, l2, l3;
    split_bf16(v.x, h0, l0); split_bf16(v.y, h1, l1);
    split_bf16(v.z, h2, l2); split_bf16(v.w, h3, l3);
    __nv_bfloat16* d = dst + (size_t)row * KT + c4;
    ((__nv_bfloat162*)(d       ))[0] = __nv_bfloat162(h0, h1);
    ((__nv_bfloat162*)(d       ))[1] = __nv_bfloat162(h2, h3);
    ((__nv_bfloat162*)(d +  512))[0] = __nv_bfloat162(h0, h1);
    ((__nv_bfloat162*)(d +  512))[1] = __nv_bfloat162(h2, h3);
    ((__nv_bfloat162*)(d + 1024))[0] = __nv_bfloat162(l0, l1);
    ((__nv_bfloat162*)(d + 1024))[1] = __nv_bfloat162(l2, l3);
}

// ---------------------------------------------------------------------------
// HMMA GEMM: C[M, Nout](fp32) = A[M, KT](bf16) @ B[Nout, KT](bf16)^T + bias
// CTA 128x128, 4 warps (2x2), warp tile 64x64, K-chunk 32, 4-stage cp.async.
// smem rows stride 80B; one barrier per K-chunk (ring-distance safe).
// Warp tile 64x64 cuts ldsm traffic 48->32 KB per chunk (MMA:LDSM 4:1).
// ---------------------------------------------------------------------------
__global__ __launch_bounds__(128, 2)
void gemm_mma(const __nv_bfloat16* __restrict__ A,
              const __nv_bfloat16* __restrict__ Bm,
              const float* __restrict__ bias, float* __restrict__ C, int Nout)
{
    extern __shared__ __align__(128) char smem[];
    const int tid  = threadIdx.x;
    const int wid  = tid >> 5;
    const int lane = tid & 31;
    const int m0 = blockIdx.y * BM;
    const int n0 = blockIdx.x * BN;
    const int warp_m = (wid >> 1) * 64;   // 0 or 64
    const int warp_n = (wid & 1) * 64;    // 0 or 64
    const uint32_t sbase = smem_u32(smem);

    // load thread mapping: 512 16B-chunks per tile, 4 per thread per tile
    const int lr = tid >> 2;        // 0..31 base row
    const int lc = tid & 3;         // 16B chunk in row

    float acc[4][8][4];
#pragma unroll
    for (int mi = 0; mi < 4; mi++)
#pragma unroll
        for (int ni = 0; ni < 8; ni++)
#pragma unroll
            for (int r = 0; r < 4; r++) acc[mi][ni][r] = 0.f;

    auto load_stage = [&](int kc, int buf) {
        const uint32_t as = sbase + buf * ST_BYTES;
        const uint32_t bs = as + A_ST;
        const __nv_bfloat16* Ag = A  + (size_t)m0 * KT + kc * BK;
        const __nv_bfloat16* Bg = Bm + (size_t)n0 * KT + kc * BK;
#pragma unroll
        for (int i = 0; i < 4; i++) {
            int r = lr + i * 32;
            cp_async16(as + r * ROWB + lc * 16, Ag + (size_t)r * KT + lc * 8);
        }
#pragma unroll
        for (int i = 0; i < 4; i++) {
            int r = lr + i * 32;
            cp_async16(bs + r * ROWB + lc * 16, Bg + (size_t)r * KT + lc * 8);
        }
        CP_COMMIT();
    };

    load_stage(0, 0);
    load_stage(1, 1);
    load_stage(2, 2);

    // fragment addresses (constant per thread, add stage/k offsets)
    const uint32_t a_addr0 = sbase + (warp_m + (lane & 15)) * ROWB + (lane >> 4) * 16;
    const uint32_t b_addr0 = sbase + A_ST
                           + (warp_n + ((lane >> 4) << 3) + (lane & 7)) * ROWB
                           + (((lane >> 3) & 1) << 4);

    for (int k = 0; k < NK; k++) {
        const int buf = k & 3;
        if (k < NK - 2)       { CP_WAIT(2); }
        else if (k == NK - 2) { CP_WAIT(1); }
        else                  { CP_WAIT(0); }
        __syncthreads();

        const uint32_t soff = buf * ST_BYTES;
#pragma unroll
        for (int ks = 0; ks < 2; ks++) {            // two k16 steps per chunk
            uint32_t af[4][4], bf[4][4];
#pragma unroll
            for (int mi = 0; mi < 4; mi++)
                ldsm4(af[mi], a_addr0 + soff + mi * 16 * ROWB + ks * 32);
#pragma unroll
            for (int nj = 0; nj < 4; nj++)
                ldsm4(bf[nj], b_addr0 + soff + nj * 16 * ROWB + ks * 32);
#pragma unroll
            for (int mi = 0; mi < 4; mi++) {
#pragma unroll
                for (int ni = 0; ni < 8; ni++) {
                    const uint32_t* bp = &bf[ni >> 1][(ni & 1) * 2];
                    mma16816(acc[mi][ni], af[mi], bp);
                }
            }
        }
        // no trailing barrier: iter-k writes target buf (k+3)&3 = (k-1)&3,
        // whose readers (iter k-1 ldsm) all passed this iter's top barrier.
        const int kn = k + 3;
        if (kn < NK) load_stage(kn, kn & 3);
    }

    // epilogue: bias + fp32 store (float2 per reg-pair)
#pragma unroll
    for (int mi = 0; mi < 4; mi++) {
#pragma unroll
        for (int ni = 0; ni < 8; ni++) {
            int row = m0 + warp_m + mi * 16 + (lane >> 2);
            int col = n0 + warp_n + ni * 8 + (lane & 3) * 2;
            float b0 = bias[col], b1 = bias[col + 1];
            float2 v0 = make_float2(acc[mi][ni][0] + b0, acc[mi][ni][1] + b1);
            float2 v1 = make_float2(acc[mi][ni][2] + b0, acc[mi][ni][3] + b1);
            *(float2*)(C + (size_t)row * Nout + col)       = v0;
            *(float2*)(C + (size_t)(row + 8) * Nout + col) = v1;
        }
    }
}

// ---------------------------------------------------------------------------
// Attention: one block per (b, h). 32 q x 32 k x 128 d. Output written
// directly in tripled-bf16 A-side layout [Ah | Al | Ah] into g_ctxa.
// ---------------------------------------------------------------------------
__global__ __launch_bounds__(128)
void attn_kernel(const float* __restrict__ qkv,
                 const unsigned char* __restrict__ pad,
                 __nv_bfloat16* __restrict__ ctxa)
{
    __shared__ float qs[32 * 129];
    __shared__ float ks[32 * 129];
    __shared__ float vs[32 * 129];
    __shared__ float sc[32 * 33];
    __shared__ int   spad[32];

    const int b = blockIdx.x >> 2;
    const int h = blockIdx.x & 3;
    const int tid = threadIdx.x;

    const float* base = qkv + (size_t)b * N_ * QKV_COLS + h * HD_;

    for (int idx = tid; idx < N_ * HD_; idx += 128) {
        int r = idx >> 7, c = idx & 127;
        qs[r * 129 + c] = base[(size_t)r * QKV_COLS            + c];
        ks[r * 129 + c] = base[(size_t)r * QKV_COLS + D_     + c];
        vs[r * 129 + c] = base[(size_t)r * QKV_COLS + 2 * D_ + c];
    }
    if (tid < 32) spad[tid] = pad[b * N_ + tid];
    __syncthreads();

    const int q = tid >> 2;
    const int kbase = (tid & 3) * 8;
    const float* qrow = &qs[q * 129];

    float acc[8];
#pragma unroll
    for (int i = 0; i < 8; i++) acc[i] = 0.f;

    for (int c0 = 0; c0 < HD_; c0 += 16) {
        float qreg[16];
#pragma unroll
        for (int c = 0; c < 16; c++) qreg[c] = qrow[c0 + c];
#pragma unroll
        for (int i = 0; i < 8; i++) {
            const float* krow = &ks[(kbase + i) * 129 + c0];
#pragma unroll
            for (int c = 0; c < 16; c++) acc[i] += qreg[c] * krow[c];
        }
    }

    const float scale = 0.08838834764831845f;  // 1/sqrt(128)
#pragma unroll
    for (int i = 0; i < 8; i++) {
        int k = kbase + i;
        float s = (k == q || spad[k]) ? -1e30f : acc[i] * scale;
        sc[q * 33 + k] = s;
    }
    __syncthreads();

    if (tid < 32) {
        float m = -1e30f;
#pragma unroll
        for (int k = 0; k < 32; k++) m = fmaxf(m, sc[tid * 33 + k]);
        float sum = 0.f;
#pragma unroll
        for (int k = 0; k < 32; k++) {
            float e = __expf(sc[tid * 33 + k] - m);
            sc[tid * 33 + k] = e;
            sum += e;
        }
        float inv = 1.f / sum;
#pragma unroll
        for (int k = 0; k < 32; k++) sc[tid * 33 + k] *= inv;
    }
    __syncthreads();

    {
        const int dq = tid & 3;
        float o[32];
#pragma unroll
        for (int j = 0; j < 32; j++) o[j] = 0.f;
        for (int k = 0; k < 32; k++) {
            float p = sc[q * 33 + k];
            const float* vrow = &vs[k * 129 + dq];
#pragma unroll
            for (int j = 0; j < 32; j++) o[j] += p * vrow[4 * j];
        }
        float* stg = &ks[q * 129 + dq];
#pragma unroll
        for (int j = 0; j < 32; j++) stg[4 * j] = o[j];
    }
    __syncthreads();

    // write tripled-bf16 ctx: [Ah | Al | Ah]
    __nv_bfloat16* outa = ctxa + (size_t)b * N_ * KT + h * HD_;
    for (int idx = tid; idx < N_ * HD_; idx += 128) {
        int r = idx >> 7, c = idx & 127;
        float v = ks[r * 129 + c];
        __nv_bfloat16 hi, lo;
        split_bf16(v, hi, lo);
        __nv_bfloat16* p = outa + (size_t)r * KT + c;
        p[0]    = hi;
        p[512]  = lo;
        p[1024] = hi;
    }
}

// ---------------------------------------------------------------------------
// Launch
// ---------------------------------------------------------------------------
extern "C" void kernel_launch(void* const* d_in, const int* in_sizes, int n_in,
                              void* d_out, int out_size)
{
    const float*         x     = (const float*)d_in[0];
    const unsigned char* pmask = (const unsigned char*)d_in[1];
    const float*         w_in  = (const float*)d_in[2];
    const float*         b_in  = (const float*)d_in[3];
    const float*         w_out = (const float*)d_in[4];
    const float*         b_out = (const float*)d_in[5];
    float*               out   = (float*)d_out;

    void *qkv_p, *xa_p, *ctxa_p, *wina_p, *wouta_p;
    cudaGetSymbolAddress(&qkv_p,   g_qkv);
    cudaGetSymbolAddress(&xa_p,    g_xa);
    cudaGetSymbolAddress(&ctxa_p,  g_ctxa);
    cudaGetSymbolAddress(&wina_p,  g_wina);
    cudaGetSymbolAddress(&wouta_p, g_wouta);
    float*         qkv   = (float*)qkv_p;
    __nv_bfloat16* xa    = (__nv_bfloat16*)xa_p;
    __nv_bfloat16* ctxa  = (__nv_bfloat16*)ctxa_p;
    __nv_bfloat16* wina  = (__nv_bfloat16*)wina_p;
    __nv_bfloat16* wouta = (__nv_bfloat16*)wouta_p;

    cudaFuncSetAttribute(gemm_mma, cudaFuncAttributeMaxDynamicSharedMemorySize,
                         GEMM_SMEM);

    // split-precision conversions
    {
        int t4 = M_ROWS * 128;
        conv_a<<<(t4 + 255) / 256, 256>>>(x, xa, t4);
    }
    {
        int t4 = QKV_COLS * 128;
        conv_b<<<(t4 + 255) / 256, 256>>>(w_in, wina, t4);
    }
    {
        int t4 = D_ * 128;
        conv_b<<<(t4 + 255) / 256, 256>>>(w_out, wouta, t4);
    }

    // 1) QKV projection: (32768 x 1536)
    {
        dim3 grid(QKV_COLS / BN, M_ROWS / BM);   // (12, 256)
        gemm_mma<<<grid, 128, GEMM_SMEM>>>(xa, wina, b_in, qkv, QKV_COLS);
    }

    // 2) attention (writes tripled-bf16 ctx)
    attn_kernel<<<B_ * H_, 128>>>(qkv, pmask, ctxa);

    // 3) output projection: (32768 x 512)
    {
        dim3 grid(D_ / BN, M_ROWS / BM);         // (4, 256)
        gemm_mma<<<grid, 128, GEMM_SMEM>>>(ctxa, wouta, b_out, out, D_);
    }
}